// round 11
// baseline (speedup 1.0000x reference)
#include <cuda_runtime.h>
#include <math.h>

#define Bb 64
#define Tt 128
#define Ii 1024
#define Hh 4096
#define NNZ_IH 262144
#define NNZ_HH 1048576
#define HB (Hh * Bb)

#define NW_HH 8              // col windows of 512 for hh
#define NW_IH 2              // col windows of 512 for ih
#define WINC 512
#define NK_HH (NW_HH * Hh)   // 32768 buckets
#define NK_IH (NW_IH * Hh)   // 8192 buckets
#define CAP 80               // fixed bucket capacity (multiple of 8)
#define NC 16                // row chunks of 256
#define NBLK 128             // persistent grid
#define TSTR 68              // smem transpose row stride (floats), 272B (%8==0)

#define SMEM_WINB (WINC * Bb * 4)          // 131072 window bytes
#define SMEM_TRB  (256 * TSTR * 4)         // 69632 transpose bytes
#define SMEM_TOT  (SMEM_WINB + SMEM_TRB)   // 200704 bytes

// ---------------- device scratch ----------------
__device__ __align__(16) float g_xT[Tt * Ii * Bb];       // (T, I, B)
__device__ __align__(16) float g_ihbT[Tt * Bb * Hh];     // ih preact, (T, B, H)
__device__ __align__(16) float g_h[HB];                  // hidden (H, B)
__device__ __align__(16) float g_partB[Bb * NW_HH * Hh]; // partials, (B, W, H)

__device__ __align__(16) int  g_hh_cnt[NK_HH];
__device__ __align__(16) int2 g_hh_pair[NK_HH * CAP];
__device__ __align__(16) int  g_ih_cnt[NK_IH];
__device__ __align__(16) int2 g_ih_pair[NK_IH * CAP];

__device__ int g_flags[NBLK];
__device__ int g_rel;

// ---------------- acquire/release primitives (no L1 flush) ----------------
__device__ __forceinline__ void st_rel(int* p, int v) {
    asm volatile("st.release.gpu.global.b32 [%0], %1;" :: "l"(p), "r"(v) : "memory");
}
__device__ __forceinline__ int ld_acq(const int* p) {
    int v;
    asm volatile("ld.acquire.gpu.global.b32 %0, [%1];" : "=r"(v) : "l"(p) : "memory");
    return v;
}

// ---------------- prep: init (zero + transpose) ----------------
__global__ void k_init(const float* __restrict__ x) {
    int bid = blockIdx.x;
    if (bid < 4096) {
        __shared__ float tile[32][Bb + 1];
        int i0 = (bid & 31) * 32;
        int t = bid >> 5;
        int tx = threadIdx.x & 31, ty = threadIdx.x >> 5;   // 32 x 8
        #pragma unroll
        for (int bq = 0; bq < 8; bq++) {
            int b = ty + 8 * bq;
            tile[tx][b] = x[((size_t)b * Tt + t) * Ii + i0 + tx];
        }
        __syncthreads();
        #pragma unroll
        for (int k = 0; k < 8; k++) {
            int idx = threadIdx.x + 256 * k;
            int iy = idx >> 6;
            int b = idx & 63;
            g_xT[((size_t)t * Ii + i0 + iy) * Bb + b] = tile[iy][b];
        }
    } else {
        int zb = bid - 4096;                    // 0..511
        int tid = zb * 256 + threadIdx.x;       // 131072 threads
        int4 z4; z4.x = z4.y = z4.z = z4.w = 0;
        const int NH4 = NK_HH * CAP / 2;        // int4 units
        const int NI4 = NK_IH * CAP / 2;
        for (int i = tid; i < NH4; i += 131072) ((int4*)g_hh_pair)[i] = z4;
        for (int i = tid; i < NI4; i += 131072) ((int4*)g_ih_pair)[i] = z4;
        float4 zf; zf.x = zf.y = zf.z = zf.w = 0.f;
        for (int i = tid; i < HB / 4; i += 131072) ((float4*)g_h)[i] = zf;
        for (int i = tid; i < NK_HH; i += 131072) g_hh_cnt[i] = 0;
        for (int i = tid; i < NK_IH; i += 131072) g_ih_cnt[i] = 0;
        if (tid < NBLK) g_flags[tid] = 0;
        if (tid == 0) g_rel = 0;
    }
}

// ---------------- prep: direct scatter into fixed-capacity buckets ----------------
__global__ void k_scatter(const int* __restrict__ hr, const int* __restrict__ hc,
                          const float* __restrict__ hv,
                          const int* __restrict__ ir, const int* __restrict__ ic,
                          const float* __restrict__ iv) {
    for (int i = blockIdx.x * blockDim.x + threadIdx.x; i < NNZ_HH + NNZ_IH;
         i += gridDim.x * blockDim.x) {
        if (i < NNZ_HH) {
            int c = hc[i];
            int key = (c >> 9) * Hh + hr[i];
            int p = atomicAdd(&g_hh_cnt[key], 1);
            if (p < CAP) {
                int2 pr; pr.x = (c & (WINC - 1)) << 8; pr.y = __float_as_int(hv[i]);
                g_hh_pair[key * CAP + p] = pr;
            }
        } else {
            int j = i - NNZ_HH;
            int c = ic[j];
            int key = (c >> 9) * Hh + ir[j];
            int p = atomicAdd(&g_ih_cnt[key], 1);
            if (p < CAP) {
                int2 pr; pr.x = (c & (WINC - 1)) << 8; pr.y = __float_as_int(iv[j]);
                g_ih_pair[key * CAP + p] = pr;
            }
        }
    }
}

// ---------------- pipelined gather of ONE bucket (low register footprint) ----------------
__device__ __forceinline__ void proc4(int4 c, const char* shb, int lane8,
                                      float& ax, float& ay) {
    float2 h0 = *(const float2*)(shb + c.x + lane8);
    float v0 = __int_as_float(c.y);
    ax = fmaf(v0, h0.x, ax);
    ay = fmaf(v0, h0.y, ay);
    float2 h1 = *(const float2*)(shb + c.z + lane8);
    float v1 = __int_as_float(c.w);
    ax = fmaf(v1, h1.x, ax);
    ay = fmaf(v1, h1.y, ay);
}

__device__ __forceinline__ void bucket8p(const int4* __restrict__ p4, int s, int e,
                                         const char* shb, int lane8,
                                         float& ax, float& ay) {
    int i4 = s >> 1, e4 = e >> 1;
    int4 n0, n1, n2, n3;
    if (i4 < e4) {
        n0 = __ldg(p4 + i4);     n1 = __ldg(p4 + i4 + 1);
        n2 = __ldg(p4 + i4 + 2); n3 = __ldg(p4 + i4 + 3);
    }
    for (; i4 < e4; i4 += 4) {
        int4 c0 = n0, c1 = n1, c2 = n2, c3 = n3;
        if (i4 + 4 < e4) {
            n0 = __ldg(p4 + i4 + 4); n1 = __ldg(p4 + i4 + 5);
            n2 = __ldg(p4 + i4 + 6); n3 = __ldg(p4 + i4 + 7);
        }
        proc4(c0, shb, lane8, ax, ay);
        proc4(c1, shb, lane8, ax, ay);
        proc4(c2, shb, lane8, ax, ay);
        proc4(c3, shb, lane8, ax, ay);
    }
}

// transposed flush: tr (256 local rows x 64 b, stride TSTR) -> dst[b][base+r]
__device__ __forceinline__ void flush_transposed(const float* tr, int tid,
                                                 float* __restrict__ dst,
                                                 size_t bstride, int base) {
    int f8 = tid >> 6;            // 0..15
    int b = tid & 63;             // 0..63 (lane-consecutive)
    #pragma unroll
    for (int j = 0; j < 4; j++) {
        int r = f8 * 16 + j * 4;
        float4 o;
        o.x = tr[(r + 0) * TSTR + b];
        o.y = tr[(r + 1) * TSTR + b];
        o.z = tr[(r + 2) * TSTR + b];
        o.w = tr[(r + 3) * TSTR + b];
        *(float4*)(dst + (size_t)b * bstride + base + r) = o;
    }
}

// ---------------- prep: windowed ih precompute over all t, emits (T,B,H) ----------------
__global__ void __launch_bounds__(1024) k_ih() {
    extern __shared__ float sh[];
    float* tr = sh + WINC * Bb;               // transpose buffer region
    int t = blockIdx.y;
    int chunk0 = blockIdx.x * 256;
    int tid = threadIdx.x;
    int lane = tid & 31, warp = tid >> 5;
    int lane8 = lane << 3;
    const char* shb = (const char*)sh;

    for (int w = 0; w < NW_IH; w++) {
        {
            const float4* src = (const float4*)(g_xT + (size_t)t * Ii * Bb + w * WINC * Bb);
            float4* dst = (float4*)sh;
            #pragma unroll
            for (int i = tid; i < WINC * Bb / 4; i += 1024) dst[i] = src[i];
        }
        __syncthreads();
        #pragma unroll 1
        for (int k = 0; k < 8; k++) {
            int rl = warp + 32 * k;           // local row 0..255
            int key = w * Hh + chunk0 + rl;
            int c = min(__ldg(&g_ih_cnt[key]), CAP);
            int s = key * CAP;
            float ax = 0.f, ay = 0.f;
            bucket8p((const int4*)g_ih_pair, s, s + ((c + 7) & ~7), shb, lane8, ax, ay);
            float2* slot = (float2*)(tr + rl * TSTR + 2 * lane);
            if (w == 0) { float2 o; o.x = ax; o.y = ay; *slot = o; }
            else { float2 o = *slot; o.x += ax; o.y += ay; *slot = o; }
        }
        __syncthreads();                       // rows done before restage / flush
    }
    flush_transposed(tr, tid, g_ihbT + (size_t)t * Bb * Hh, Hh, chunk0);
}

// ---------------- central-release barrier, acquire/release only ----------------
__device__ __forceinline__ void gbar(int& epoch, int bid, int tid) {
    epoch++;
    __syncthreads();
    if (tid == 0) st_rel(&g_flags[bid], epoch);
    if (bid == 0) {
        if (tid < NBLK) {
            while (ld_acq(&g_flags[tid]) < epoch) __nanosleep(32);
        }
        __syncthreads();
        if (tid == 0) st_rel(&g_rel, epoch);
    } else {
        if (tid == 0) {
            while (ld_acq(&g_rel) < epoch) __nanosleep(32);
        }
    }
    __syncthreads();
}

// ---------------- persistent recurrence: 2 phases, 2 barriers, low reg pressure ----------------
__global__ void __launch_bounds__(1024) k_persist(const float* __restrict__ b_ih,
                                                  const float* __restrict__ b_hh,
                                                  const float* __restrict__ gamma,
                                                  const float* __restrict__ beta,
                                                  float* __restrict__ out) {
    extern __shared__ float sh[];
    float* tr = sh + WINC * Bb;           // transpose buffer region
    int bid = blockIdx.x;                 // 0..127
    int w = bid >> 4;                     // window 0..7
    int chunk0 = (bid & 15) * 256;        // row chunk
    int tid = threadIdx.x;
    int lane = tid & 31, warp = tid >> 5;
    int lane8 = lane << 3;
    const char* shb = (const char*)sh;
    int epoch = 0;

    for (int t = 0; t < Tt; t++) {
        // ---- phase A: stage h window, per-row gather -> tr, transposed flush ----
        {
            const float4* src = (const float4*)(g_h + w * WINC * Bb);
            float4* dst = (float4*)sh;
            #pragma unroll
            for (int i = tid; i < WINC * Bb / 4; i += 1024) dst[i] = __ldcg(src + i);
        }
        __syncthreads();
        #pragma unroll 1
        for (int k = 0; k < 8; k++) {
            int rl = warp + 32 * k;            // local row 0..255
            int key = w * Hh + chunk0 + rl;
            int c = min(__ldg(&g_hh_cnt[key]), CAP);
            int s = key * CAP;
            float ax = 0.f, ay = 0.f;
            bucket8p((const int4*)g_hh_pair, s, s + ((c + 7) & ~7), shb, lane8, ax, ay);
            float2 o; o.x = ax; o.y = ay;
            *(float2*)(tr + rl * TSTR + 2 * lane) = o;
        }
        __syncthreads();
        flush_transposed(tr, tid, g_partB, (size_t)(NW_HH * Hh), w * Hh + chunk0);
        gbar(epoch, bid, tid);

        // ---- phase C: fused reduce + bias + tanh + LN (blocks 0..63) ----
        if (bid < Bb) {
            int b = bid;
            __shared__ float s1[32], s2[32];
            const float4* pb = (const float4*)(g_partB + (size_t)b * NW_HH * Hh);
            float4 v = __ldcg((const float4*)(g_ihbT + ((size_t)t * Bb + b) * Hh) + tid);
            {
                float4 bi = ((const float4*)b_ih)[tid];
                float4 bh = ((const float4*)b_hh)[tid];
                v.x += bi.x + bh.x; v.y += bi.y + bh.y;
                v.z += bi.z + bh.z; v.w += bi.w + bh.w;
            }
            #pragma unroll 4
            for (int ww = 0; ww < NW_HH; ww++) {
                float4 p = __ldcg(pb + ww * (Hh / 4) + tid);
                v.x += p.x; v.y += p.y; v.z += p.z; v.w += p.w;
            }
            v.x = tanhf(v.x); v.y = tanhf(v.y);
            v.z = tanhf(v.z); v.w = tanhf(v.w);
            float sum = v.x + v.y + v.z + v.w;
            float sq = v.x * v.x + v.y * v.y + v.z * v.z + v.w * v.w;
            #pragma unroll
            for (int o = 16; o > 0; o >>= 1) {
                sum += __shfl_down_sync(0xffffffffu, sum, o);
                sq  += __shfl_down_sync(0xffffffffu, sq, o);
            }
            if (lane == 0) { s1[warp] = sum; s2[warp] = sq; }
            __syncthreads();
            if (warp == 0) {
                sum = s1[lane]; sq = s2[lane];
                #pragma unroll
                for (int o = 16; o > 0; o >>= 1) {
                    sum += __shfl_down_sync(0xffffffffu, sum, o);
                    sq  += __shfl_down_sync(0xffffffffu, sq, o);
                }
                if (lane == 0) { s1[0] = sum; s2[0] = sq; }
            }
            __syncthreads();
            float mu = s1[0] * (1.0f / Hh);
            float var = s2[0] * (1.0f / Hh) - mu * mu;
            float rs = rsqrtf(var + 1e-5f);
            int r4 = tid * 4;
            float4 g = ((const float4*)gamma)[tid];
            float4 be4 = ((const float4*)beta)[tid];
            float4 hn;
            hn.x = (v.x - mu) * rs * g.x + be4.x;
            hn.y = (v.y - mu) * rs * g.y + be4.y;
            hn.z = (v.z - mu) * rs * g.z + be4.z;
            hn.w = (v.w - mu) * rs * g.w + be4.w;
            *(float4*)(out + ((size_t)b * Tt + t) * Hh + r4) = hn;
            g_h[(r4 + 0) * Bb + b] = hn.x;
            g_h[(r4 + 1) * Bb + b] = hn.y;
            g_h[(r4 + 2) * Bb + b] = hn.z;
            g_h[(r4 + 3) * Bb + b] = hn.w;
            if (t == Tt - 1)
                *(float4*)(out + (size_t)Bb * Tt * Hh + (size_t)b * Hh + r4) = hn;
        }
        gbar(epoch, bid, tid);
    }
}

// ---------------- launch ----------------
extern "C" void kernel_launch(void* const* d_in, const int* in_sizes, int n_in,
                              void* d_out, int out_size) {
    const float* x       = (const float*)d_in[0];
    const int*   ih_rows = (const int*)d_in[1];
    const int*   ih_cols = (const int*)d_in[2];
    const float* ih_vals = (const float*)d_in[3];
    const int*   hh_rows = (const int*)d_in[4];
    const int*   hh_cols = (const int*)d_in[5];
    const float* hh_vals = (const float*)d_in[6];
    const float* b_ih    = (const float*)d_in[7];
    const float* b_hh    = (const float*)d_in[8];
    const float* gamma   = (const float*)d_in[9];
    const float* beta    = (const float*)d_in[10];
    float* out = (float*)d_out;

    cudaFuncSetAttribute(k_ih, cudaFuncAttributeMaxDynamicSharedMemorySize, SMEM_TOT);
    cudaFuncSetAttribute(k_persist, cudaFuncAttributeMaxDynamicSharedMemorySize, SMEM_TOT);

    // 3 prep launches, then the persistent kernel
    k_init<<<4096 + 512, 256>>>(x);
    k_scatter<<<2048, 256>>>(hh_rows, hh_cols, hh_vals, ih_rows, ih_cols, ih_vals);
    k_ih<<<dim3(NC, Tt), 1024, SMEM_TOT>>>();
    k_persist<<<NBLK, 1024, SMEM_TOT>>>(b_ih, b_hh, gamma, beta, out);
}

// round 13
// speedup vs baseline: 1.2384x; 1.2384x over previous
#include <cuda_runtime.h>
#include <cuda_fp16.h>
#include <math.h>

#define Bb 64
#define Tt 128
#define Ii 1024
#define Hh 4096
#define NNZ_IH 262144
#define NNZ_HH 1048576
#define HB (Hh * Bb)

// hh: 4 windows of 1024 cols, fp16 operand window (128KB smem)
#define NW_HH 4
#define WINC_HH 1024
#define NK_HH (NW_HH * Hh)    // 16384 buckets, mean 64
#define CAP_HH 112            // Poisson(64)+6sigma, multiple of 8
// ih: 2 windows of 512 cols, fp32 (prep only)
#define NW_IH 2
#define WINC_IH 512
#define NK_IH (NW_IH * Hh)    // 8192 buckets, mean 32
#define CAP_IH 80
#define NBLK 128              // persistent grid: 4 windows x 32 chunks of 128 rows
#define TSTR 68               // smem transpose row stride (floats), 272B (%8==0)

#define SMEM_P (WINC_HH * Bb * 2 + 128 * TSTR * 4)   // 131072 + 34816 = 165888
#define SMEM_I (WINC_IH * Bb * 4 + 256 * TSTR * 4)   // 131072 + 69632 = 200704

// ---------------- device scratch ----------------
__device__ __align__(16) float  g_xT[Tt * Ii * Bb];       // (T, I, B)
__device__ __align__(16) float  g_ihbT[Tt * Bb * Hh];     // ih preact, (T, B, H)
__device__ __align__(16) __half g_h16[Hh * Bb];           // hidden fp16, (H, B)
__device__ __align__(16) float  g_partB[Bb * NW_HH * Hh]; // partials, (B, W, H)

__device__ __align__(16) int  g_hh_cnt[NK_HH];
__device__ __align__(16) int2 g_hh_pair[NK_HH * CAP_HH];  // ~14.7MB
__device__ __align__(16) int  g_ih_cnt[NK_IH];
__device__ __align__(16) int2 g_ih_pair[NK_IH * CAP_IH];  // ~5.2MB

__device__ int g_flags[NBLK];
__device__ int g_rel;

// ---------------- acquire/release primitives (no L1 flush) ----------------
__device__ __forceinline__ void st_rel(int* p, int v) {
    asm volatile("st.release.gpu.global.b32 [%0], %1;" :: "l"(p), "r"(v) : "memory");
}
__device__ __forceinline__ int ld_acq(const int* p) {
    int v;
    asm volatile("ld.acquire.gpu.global.b32 %0, [%1];" : "=r"(v) : "l"(p) : "memory");
    return v;
}

// ---------------- prep: init (zero + transpose) ----------------
__global__ void k_init(const float* __restrict__ x) {
    int bid = blockIdx.x;
    if (bid < 4096) {
        __shared__ float tile[32][Bb + 1];
        int i0 = (bid & 31) * 32;
        int t = bid >> 5;
        int tx = threadIdx.x & 31, ty = threadIdx.x >> 5;   // 32 x 8
        #pragma unroll
        for (int bq = 0; bq < 8; bq++) {
            int b = ty + 8 * bq;
            tile[tx][b] = x[((size_t)b * Tt + t) * Ii + i0 + tx];
        }
        __syncthreads();
        #pragma unroll
        for (int k = 0; k < 8; k++) {
            int idx = threadIdx.x + 256 * k;
            int iy = idx >> 6;
            int b = idx & 63;
            g_xT[((size_t)t * Ii + i0 + iy) * Bb + b] = tile[iy][b];
        }
    } else {
        int zb = bid - 4096;                    // 0..511
        int tid = zb * 256 + threadIdx.x;       // 131072 threads
        int4 z4; z4.x = z4.y = z4.z = z4.w = 0;
        const int NH4 = NK_HH * CAP_HH / 2;     // int4 units of pair arrays
        const int NI4 = NK_IH * CAP_IH / 2;
        for (int i = tid; i < NH4; i += 131072) ((int4*)g_hh_pair)[i] = z4;
        for (int i = tid; i < NI4; i += 131072) ((int4*)g_ih_pair)[i] = z4;
        for (int i = tid; i < HB / 8; i += 131072) ((int4*)g_h16)[i] = z4;  // h=0
        for (int i = tid; i < NK_HH; i += 131072) g_hh_cnt[i] = 0;
        for (int i = tid; i < NK_IH; i += 131072) g_ih_cnt[i] = 0;
        if (tid < NBLK) g_flags[tid] = 0;
        if (tid == 0) g_rel = 0;
    }
}

// ---------------- prep: direct scatter into fixed-capacity buckets ----------------
__global__ void k_scatter(const int* __restrict__ hr, const int* __restrict__ hc,
                          const float* __restrict__ hv,
                          const int* __restrict__ ir, const int* __restrict__ ic,
                          const float* __restrict__ iv) {
    for (int i = blockIdx.x * blockDim.x + threadIdx.x; i < NNZ_HH + NNZ_IH;
         i += gridDim.x * blockDim.x) {
        if (i < NNZ_HH) {
            int c = hc[i];
            int key = (c >> 10) * Hh + hr[i];            // 1024-col windows
            int p = atomicAdd(&g_hh_cnt[key], 1);
            if (p < CAP_HH) {
                int2 pr; pr.x = (c & (WINC_HH - 1)) << 7; // fp16 row = 128B
                pr.y = __float_as_int(hv[i]);
                g_hh_pair[key * CAP_HH + p] = pr;
            }
        } else {
            int j = i - NNZ_HH;
            int c = ic[j];
            int key = (c >> 9) * Hh + ir[j];             // 512-col windows
            int p = atomicAdd(&g_ih_cnt[key], 1);
            if (p < CAP_IH) {
                int2 pr; pr.x = (c & (WINC_IH - 1)) << 8; // fp32 row = 256B
                pr.y = __float_as_int(iv[j]);
                g_ih_pair[key * CAP_IH + p] = pr;
            }
        }
    }
}

// ---------------- fp32 gather core (ih prep) ----------------
__device__ __forceinline__ void proc4f(int4 c, const char* shb, int lane8,
                                       float& ax, float& ay) {
    float2 h0 = *(const float2*)(shb + c.x + lane8);
    float v0 = __int_as_float(c.y);
    ax = fmaf(v0, h0.x, ax);
    ay = fmaf(v0, h0.y, ay);
    float2 h1 = *(const float2*)(shb + c.z + lane8);
    float v1 = __int_as_float(c.w);
    ax = fmaf(v1, h1.x, ax);
    ay = fmaf(v1, h1.y, ay);
}

__device__ __forceinline__ void bucket8f(const int4* __restrict__ p4, int s, int e,
                                         const char* shb, int lane8,
                                         float& ax, float& ay) {
    int i4 = s >> 1, e4 = e >> 1;
    int4 n0, n1, n2, n3;
    if (i4 < e4) {
        n0 = __ldg(p4 + i4);     n1 = __ldg(p4 + i4 + 1);
        n2 = __ldg(p4 + i4 + 2); n3 = __ldg(p4 + i4 + 3);
    }
    for (; i4 < e4; i4 += 4) {
        int4 c0 = n0, c1 = n1, c2 = n2, c3 = n3;
        if (i4 + 4 < e4) {
            n0 = __ldg(p4 + i4 + 4); n1 = __ldg(p4 + i4 + 5);
            n2 = __ldg(p4 + i4 + 6); n3 = __ldg(p4 + i4 + 7);
        }
        proc4f(c0, shb, lane8, ax, ay);
        proc4f(c1, shb, lane8, ax, ay);
        proc4f(c2, shb, lane8, ax, ay);
        proc4f(c3, shb, lane8, ax, ay);
    }
}

// ---------------- fp16 gather core (hh recurrent) ----------------
__device__ __forceinline__ void proc4h(int4 c, const char* shb, int lane4,
                                       float& ax, float& ay) {
    __half2 h0 = *(const __half2*)(shb + c.x + lane4);
    float2 f0 = __half22float2(h0);
    float v0 = __int_as_float(c.y);
    ax = fmaf(v0, f0.x, ax);
    ay = fmaf(v0, f0.y, ay);
    __half2 h1 = *(const __half2*)(shb + c.z + lane4);
    float2 f1 = __half22float2(h1);
    float v1 = __int_as_float(c.w);
    ax = fmaf(v1, f1.x, ax);
    ay = fmaf(v1, f1.y, ay);
}

__device__ __forceinline__ void bucket8h(const int4* __restrict__ p4, int s, int e,
                                         const char* shb, int lane4,
                                         float& ax, float& ay) {
    int i4 = s >> 1, e4 = e >> 1;
    int4 n0, n1, n2, n3;
    if (i4 < e4) {
        n0 = __ldg(p4 + i4);     n1 = __ldg(p4 + i4 + 1);
        n2 = __ldg(p4 + i4 + 2); n3 = __ldg(p4 + i4 + 3);
    }
    for (; i4 < e4; i4 += 4) {
        int4 c0 = n0, c1 = n1, c2 = n2, c3 = n3;
        if (i4 + 4 < e4) {
            n0 = __ldg(p4 + i4 + 4); n1 = __ldg(p4 + i4 + 5);
            n2 = __ldg(p4 + i4 + 6); n3 = __ldg(p4 + i4 + 7);
        }
        proc4h(c0, shb, lane4, ax, ay);
        proc4h(c1, shb, lane4, ax, ay);
        proc4h(c2, shb, lane4, ax, ay);
        proc4h(c3, shb, lane4, ax, ay);
    }
}

// ---------------- prep: windowed ih precompute over all t, emits (T,B,H) ----------------
__global__ void __launch_bounds__(1024) k_ih() {
    extern __shared__ float sh[];
    float* tr = sh + WINC_IH * Bb;            // transpose buffer (256 rows)
    int t = blockIdx.y;
    int chunk0 = blockIdx.x * 256;
    int tid = threadIdx.x;
    int lane = tid & 31, warp = tid >> 5;
    int lane8 = lane << 3;
    const char* shb = (const char*)sh;

    for (int w = 0; w < NW_IH; w++) {
        {
            const float4* src = (const float4*)(g_xT + (size_t)t * Ii * Bb + w * WINC_IH * Bb);
            float4* dst = (float4*)sh;
            #pragma unroll
            for (int i = tid; i < WINC_IH * Bb / 4; i += 1024) dst[i] = src[i];
        }
        __syncthreads();
        #pragma unroll 1
        for (int k = 0; k < 8; k++) {
            int rl = warp + 32 * k;           // local row 0..255
            int key = w * Hh + chunk0 + rl;
            int c = min(__ldg(&g_ih_cnt[key]), CAP_IH);
            int s = key * CAP_IH;
            float ax = 0.f, ay = 0.f;
            bucket8f((const int4*)g_ih_pair, s, s + ((c + 7) & ~7), shb, lane8, ax, ay);
            float2* slot = (float2*)(tr + rl * TSTR + 2 * lane);
            if (w == 0) { float2 o; o.x = ax; o.y = ay; *slot = o; }
            else { float2 o = *slot; o.x += ax; o.y += ay; *slot = o; }
        }
        __syncthreads();
    }
    // flush 256 rows transposed -> g_ihbT[t][b][chunk0 + r]
    {
        float* dst = g_ihbT + (size_t)t * Bb * Hh;
        int f8 = tid >> 6;            // 0..15
        int b = tid & 63;
        #pragma unroll
        for (int j = 0; j < 4; j++) {
            int r = f8 * 16 + j * 4;
            float4 o;
            o.x = tr[(r + 0) * TSTR + b];
            o.y = tr[(r + 1) * TSTR + b];
            o.z = tr[(r + 2) * TSTR + b];
            o.w = tr[(r + 3) * TSTR + b];
            *(float4*)(dst + (size_t)b * Hh + chunk0 + r) = o;
        }
    }
}

// ---------------- central-release barrier, acquire/release only ----------------
__device__ __forceinline__ void gbar(int& epoch, int bid, int tid) {
    epoch++;
    __syncthreads();
    if (tid == 0) st_rel(&g_flags[bid], epoch);
    if (bid == 0) {
        if (tid < NBLK) {
            while (ld_acq(&g_flags[tid]) < epoch) __nanosleep(32);
        }
        __syncthreads();
        if (tid == 0) st_rel(&g_rel, epoch);
    } else {
        if (tid == 0) {
            while (ld_acq(&g_rel) < epoch) __nanosleep(32);
        }
    }
    __syncthreads();
}

// ---------------- persistent recurrence: fp16 window, 2 phases, 2 barriers ----------------
__global__ void __launch_bounds__(1024) k_persist(const float* __restrict__ b_ih,
                                                  const float* __restrict__ b_hh,
                                                  const float* __restrict__ gamma,
                                                  const float* __restrict__ beta,
                                                  float* __restrict__ out) {
    extern __shared__ float shf[];
    char* shb = (char*)shf;                       // fp16 window, 131072 bytes
    float* tr = shf + WINC_HH * Bb / 2;           // transpose buffer (128 rows)
    int bid = blockIdx.x;                 // 0..127
    int w = bid >> 5;                     // window 0..3
    int chunk0 = (bid & 31) * 128;        // row chunk of 128
    int tid = threadIdx.x;
    int lane = tid & 31, warp = tid >> 5;
    int lane4 = lane << 2;
    int epoch = 0;

    for (int t = 0; t < Tt; t++) {
        // ---- phase A: stage fp16 window (raw copy), gather, transposed flush ----
        {
            const uint4* src = (const uint4*)(g_h16 + (size_t)w * WINC_HH * Bb);
            uint4* dst = (uint4*)shb;
            #pragma unroll
            for (int i = tid; i < WINC_HH * Bb * 2 / 16; i += 1024)
                dst[i] = __ldcg(src + i);
        }
        __syncthreads();
        #pragma unroll 1
        for (int k = 0; k < 4; k++) {
            int rl = warp + 32 * k;            // local row 0..127
            int key = w * Hh + chunk0 + rl;
            int c = min(__ldg(&g_hh_cnt[key]), CAP_HH);
            int s = key * CAP_HH;
            float ax = 0.f, ay = 0.f;
            bucket8h((const int4*)g_hh_pair, s, s + ((c + 7) & ~7), shb, lane4, ax, ay);
            float2 o; o.x = ax; o.y = ay;
            *(float2*)(tr + rl * TSTR + 2 * lane) = o;
        }
        __syncthreads();
        // flush 128 rows transposed -> g_partB[b][w*Hh + chunk0 + r]
        {
            int f8 = tid >> 6;            // 0..15
            int b = tid & 63;
            #pragma unroll
            for (int j = 0; j < 2; j++) {
                int r = f8 * 8 + j * 4;
                float4 o;
                o.x = tr[(r + 0) * TSTR + b];
                o.y = tr[(r + 1) * TSTR + b];
                o.z = tr[(r + 2) * TSTR + b];
                o.w = tr[(r + 3) * TSTR + b];
                *(float4*)(g_partB + (size_t)b * (NW_HH * Hh) + w * Hh + chunk0 + r) = o;
            }
        }
        gbar(epoch, bid, tid);

        // ---- phase C: fused reduce + bias + tanh + LN (blocks 0..63) ----
        if (bid < Bb) {
            int b = bid;
            __shared__ float s1[32], s2[32];
            const float4* pb = (const float4*)(g_partB + (size_t)b * NW_HH * Hh);
            float4 v = __ldcg((const float4*)(g_ihbT + ((size_t)t * Bb + b) * Hh) + tid);
            {
                float4 bi = ((const float4*)b_ih)[tid];
                float4 bh = ((const float4*)b_hh)[tid];
                v.x += bi.x + bh.x; v.y += bi.y + bh.y;
                v.z += bi.z + bh.z; v.w += bi.w + bh.w;
            }
            #pragma unroll
            for (int ww = 0; ww < NW_HH; ww++) {
                float4 p = __ldcg(pb + ww * (Hh / 4) + tid);
                v.x += p.x; v.y += p.y; v.z += p.z; v.w += p.w;
            }
            v.x = tanhf(v.x); v.y = tanhf(v.y);
            v.z = tanhf(v.z); v.w = tanhf(v.w);
            float sum = v.x + v.y + v.z + v.w;
            float sq = v.x * v.x + v.y * v.y + v.z * v.z + v.w * v.w;
            #pragma unroll
            for (int o = 16; o > 0; o >>= 1) {
                sum += __shfl_down_sync(0xffffffffu, sum, o);
                sq  += __shfl_down_sync(0xffffffffu, sq, o);
            }
            if (lane == 0) { s1[warp] = sum; s2[warp] = sq; }
            __syncthreads();
            if (warp == 0) {
                sum = s1[lane]; sq = s2[lane];
                #pragma unroll
                for (int o = 16; o > 0; o >>= 1) {
                    sum += __shfl_down_sync(0xffffffffu, sum, o);
                    sq  += __shfl_down_sync(0xffffffffu, sq, o);
                }
                if (lane == 0) { s1[0] = sum; s2[0] = sq; }
            }
            __syncthreads();
            float mu = s1[0] * (1.0f / Hh);
            float var = s2[0] * (1.0f / Hh) - mu * mu;
            float rs = rsqrtf(var + 1e-5f);
            int r4 = tid * 4;
            float4 g = ((const float4*)gamma)[tid];
            float4 be4 = ((const float4*)beta)[tid];
            float4 hn;
            hn.x = (v.x - mu) * rs * g.x + be4.x;
            hn.y = (v.y - mu) * rs * g.y + be4.y;
            hn.z = (v.z - mu) * rs * g.z + be4.z;
            hn.w = (v.w - mu) * rs * g.w + be4.w;
            *(float4*)(out + ((size_t)b * Tt + t) * Hh + r4) = hn;
            // next-step hidden, fp16, (H,B) layout
            g_h16[(r4 + 0) * Bb + b] = __float2half_rn(hn.x);
            g_h16[(r4 + 1) * Bb + b] = __float2half_rn(hn.y);
            g_h16[(r4 + 2) * Bb + b] = __float2half_rn(hn.z);
            g_h16[(r4 + 3) * Bb + b] = __float2half_rn(hn.w);
            if (t == Tt - 1)
                *(float4*)(out + (size_t)Bb * Tt * Hh + (size_t)b * Hh + r4) = hn;
        }
        gbar(epoch, bid, tid);
    }
}

// ---------------- launch ----------------
extern "C" void kernel_launch(void* const* d_in, const int* in_sizes, int n_in,
                              void* d_out, int out_size) {
    const float* x       = (const float*)d_in[0];
    const int*   ih_rows = (const int*)d_in[1];
    const int*   ih_cols = (const int*)d_in[2];
    const float* ih_vals = (const float*)d_in[3];
    const int*   hh_rows = (const int*)d_in[4];
    const int*   hh_cols = (const int*)d_in[5];
    const float* hh_vals = (const float*)d_in[6];
    const float* b_ih    = (const float*)d_in[7];
    const float* b_hh    = (const float*)d_in[8];
    const float* gamma   = (const float*)d_in[9];
    const float* beta    = (const float*)d_in[10];
    float* out = (float*)d_out;

    cudaFuncSetAttribute(k_ih, cudaFuncAttributeMaxDynamicSharedMemorySize, SMEM_I);
    cudaFuncSetAttribute(k_persist, cudaFuncAttributeMaxDynamicSharedMemorySize, SMEM_P);

    // 3 prep launches, then the persistent kernel
    k_init<<<4096 + 512, 256>>>(x);
    k_scatter<<<2048, 256>>>(hh_rows, hh_cols, hh_vals, ih_rows, ih_cols, ih_vals);
    k_ih<<<dim3(16, Tt), 1024, SMEM_I>>>();
    k_persist<<<NBLK, 1024, SMEM_P>>>(b_ih, b_hh, gamma, beta, out);
}